// round 1
// baseline (speedup 1.0000x reference)
#include <cuda_runtime.h>
#include <cuda_bf16.h>
#include <math.h>

// Problem constants
#define LNUM 12
#define E 1024
#define H 16
#define T 512
#define BATCH 8
#define VOCAB 512
#define FF 4096
#define D 64
#define BT (BATCH*T)   // 4096

// -------------------- persistent device scratch --------------------
__device__ float g_h [BT*E];
__device__ float g_xn[BT*E];
__device__ float g_q [BT*E];
__device__ float g_k [BT*E];
__device__ float g_v [BT*E];
__device__ float g_y [BT*E];
__device__ float g_ff[(size_t)BT*FF];

// -------------------- embedding --------------------
__global__ void embed_kernel(const int* __restrict__ x,
                             const float* __restrict__ tok,
                             const float* __restrict__ pos,
                             float* __restrict__ h)
{
    int idx = blockIdx.x * blockDim.x + threadIdx.x;
    if (idx >= BT*E) return;
    int row = idx >> 10;       // /E
    int e   = idx & (E-1);
    int t   = row & (T-1);
    h[idx] = tok[(size_t)x[row]*E + e] + pos[(size_t)t*E + e];
}

// -------------------- layernorm --------------------
__global__ __launch_bounds__(256) void ln_kernel(const float* __restrict__ in,
                                                 float* __restrict__ out,
                                                 const float* __restrict__ gamma,
                                                 const float* __restrict__ beta)
{
    int row = blockIdx.x;
    const float* xr = in + (size_t)row * E;
    float s = 0.f, ss = 0.f;
    for (int i = threadIdx.x; i < E; i += 256) {
        float v = xr[i]; s += v; ss += v * v;
    }
    #pragma unroll
    for (int o = 16; o > 0; o >>= 1) {
        s  += __shfl_xor_sync(0xffffffffu, s,  o);
        ss += __shfl_xor_sync(0xffffffffu, ss, o);
    }
    __shared__ float sred[8], ssred[8];
    int w = threadIdx.x >> 5;
    if ((threadIdx.x & 31) == 0) { sred[w] = s; ssred[w] = ss; }
    __syncthreads();
    if (threadIdx.x < 32) {
        s  = (threadIdx.x < 8) ? sred [threadIdx.x] : 0.f;
        ss = (threadIdx.x < 8) ? ssred[threadIdx.x] : 0.f;
        #pragma unroll
        for (int o = 4; o > 0; o >>= 1) {
            s  += __shfl_xor_sync(0xffffffffu, s,  o);
            ss += __shfl_xor_sync(0xffffffffu, ss, o);
        }
        if (threadIdx.x == 0) { sred[0] = s; ssred[0] = ss; }
    }
    __syncthreads();
    float mu   = sred[0] * (1.f / E);
    float var  = ssred[0] * (1.f / E) - mu * mu;
    float rstd = rsqrtf(var + 1e-5f);
    float* orow = out + (size_t)row * E;
    for (int i = threadIdx.x; i < E; i += 256)
        orow[i] = (xr[i] - mu) * rstd * gamma[i] + beta[i];
}

// -------------------- generic 128x128x8 SGEMM --------------------
// C[M,N] = A[M,K] @ B[K,N] (+bias) (+epilogue). All dims multiples of tile.
#define EPI_BIAS 0
#define EPI_GELU 1
#define EPI_RES  2

template<int EPI>
__global__ __launch_bounds__(256) void gemm128(int M, int N, int K,
    const float* __restrict__ A, const float* __restrict__ Bw,
    const float* __restrict__ bias, const float* __restrict__ res,
    float* __restrict__ C)
{
    __shared__ float As[8][128];
    __shared__ float Bs[8][128];
    int tid = threadIdx.x;
    int tr = tid >> 4, tc = tid & 15;
    const size_t arow0 = (size_t)blockIdx.y * 128;
    const int    bcol0 = blockIdx.x * 128;

    int aRow = tid >> 1, aCol = (tid & 1) * 4;
    int bRow = tid >> 5, bCol = (tid & 31) * 4;
    const float* Ap = A  + (arow0 + aRow) * (size_t)K + aCol;
    const float* Bp = Bw + (size_t)bRow * N + bcol0 + bCol;

    float acc[8][8];
    #pragma unroll
    for (int i = 0; i < 8; i++)
        #pragma unroll
        for (int j = 0; j < 8; j++) acc[i][j] = 0.f;

    for (int k0 = 0; k0 < K; k0 += 8) {
        float4 a4 = *(const float4*)(Ap + k0);
        As[aCol+0][aRow] = a4.x; As[aCol+1][aRow] = a4.y;
        As[aCol+2][aRow] = a4.z; As[aCol+3][aRow] = a4.w;
        float4 b4 = *(const float4*)(Bp + (size_t)k0 * N);
        *(float4*)&Bs[bRow][bCol] = b4;
        __syncthreads();
        #pragma unroll
        for (int kk = 0; kk < 8; kk++) {
            float ar[8], br[8];
            #pragma unroll
            for (int i = 0; i < 8; i++) ar[i] = As[kk][tr*8 + i];
            #pragma unroll
            for (int j = 0; j < 8; j++) br[j] = Bs[kk][tc*8 + j];
            #pragma unroll
            for (int i = 0; i < 8; i++)
                #pragma unroll
                for (int j = 0; j < 8; j++)
                    acc[i][j] = fmaf(ar[i], br[j], acc[i][j]);
        }
        __syncthreads();
    }

    #pragma unroll
    for (int i = 0; i < 8; i++) {
        size_t row = arow0 + tr*8 + i;
        #pragma unroll
        for (int j = 0; j < 8; j++) {
            int col = bcol0 + tc*8 + j;
            float v = acc[i][j];
            if (bias) v += bias[col];
            if (EPI == EPI_GELU) v = 0.5f * v * (1.f + erff(v * 0.70710678118654752f));
            if (EPI == EPI_RES)  v += res[row * (size_t)N + col];
            C[row * (size_t)N + col] = v;
        }
    }
}

// -------------------- fused causal attention (flash-style, fp32) --------------------
// Q,K,V,Y layout: [B*T, E] with head h occupying columns [h*D, (h+1)*D).
// Block: 256 threads; handles one (b,h) and a 64-row Q tile.
// thread -> q-row r = tid/4, d-quarter c4 = tid%4 (16 dims each).
__global__ __launch_bounds__(256) void attn_kernel(const float* __restrict__ Q,
                                                   const float* __restrict__ K,
                                                   const float* __restrict__ V,
                                                   float* __restrict__ Y)
{
    int bh = blockIdx.y;
    int b  = bh >> 4;      // /H
    int h  = bh & 15;
    int qt = blockIdx.x;
    int tid = threadIdx.x;
    int r  = tid >> 2;
    int c4 = tid & 3;

    __shared__ float sK[64][D];
    __shared__ float sV[64][D];

    int qrow = qt * 64 + r;
    const float* qp = Q + ((size_t)(b*T + qrow)) * E + h*D + c4*16;
    float qreg[16];
    #pragma unroll
    for (int i = 0; i < 16; i++) qreg[i] = qp[i] * 0.125f;   // 1/sqrt(64)

    float acc[16];
    #pragma unroll
    for (int i = 0; i < 16; i++) acc[i] = 0.f;
    float mcur = -INFINITY, l = 0.f;

    for (int kt = 0; kt <= qt; kt++) {
        __syncthreads();
        #pragma unroll 4
        for (int i = tid; i < 64*64; i += 256) {
            int kr = i >> 6, kc = i & 63;
            size_t g = ((size_t)(b*T + kt*64 + kr)) * E + h*D + kc;
            sK[kr][kc] = K[g];
            sV[kr][kc] = V[g];
        }
        __syncthreads();

        float s[64];
        #pragma unroll
        for (int k = 0; k < 64; k++) {
            float d = 0.f;
            #pragma unroll
            for (int i = 0; i < 16; i++)
                d = fmaf(qreg[i], sK[k][c4*16 + i], d);
            d += __shfl_xor_sync(0xffffffffu, d, 1);
            d += __shfl_xor_sync(0xffffffffu, d, 2);
            s[k] = d;
        }
        if (kt == qt) {
            #pragma unroll
            for (int k = 0; k < 64; k++)
                if (kt*64 + k > qrow) s[k] = -INFINITY;
        }
        float tmax = mcur;
        #pragma unroll
        for (int k = 0; k < 64; k++) tmax = fmaxf(tmax, s[k]);
        float fac = expf(mcur - tmax);
        mcur = tmax;
        l *= fac;
        #pragma unroll
        for (int i = 0; i < 16; i++) acc[i] *= fac;
        #pragma unroll
        for (int k = 0; k < 64; k++) {
            float p = expf(s[k] - mcur);
            l += p;
            #pragma unroll
            for (int i = 0; i < 16; i++)
                acc[i] = fmaf(p, sV[k][c4*16 + i], acc[i]);
        }
    }

    float inv = 1.f / l;
    float* yp = Y + ((size_t)(b*T + qrow)) * E + h*D + c4*16;
    #pragma unroll
    for (int i = 0; i < 16; i++) yp[i] = acc[i] * inv;
}

// -------------------- host orchestration --------------------
extern "C" void kernel_launch(void* const* d_in, const int* in_sizes, int n_in,
                              void* d_out, int out_size)
{
    (void)in_sizes; (void)n_in; (void)out_size;
    const int*   x     = (const int*)  d_in[0];
    // d_in[1] = targets (unused)
    const float* tok   = (const float*)d_in[2];
    const float* pos   = (const float*)d_in[3];
    const float* ln1_g = (const float*)d_in[4];
    const float* ln1_b = (const float*)d_in[5];
    const float* Wq    = (const float*)d_in[6];
    const float* bq    = (const float*)d_in[7];
    const float* Wk    = (const float*)d_in[8];
    const float* bk    = (const float*)d_in[9];
    const float* Wv    = (const float*)d_in[10];
    const float* bv    = (const float*)d_in[11];
    const float* Wp    = (const float*)d_in[12];
    const float* bp    = (const float*)d_in[13];
    const float* ln2_g = (const float*)d_in[14];
    const float* ln2_b = (const float*)d_in[15];
    const float* Wf1   = (const float*)d_in[16];
    const float* bf1   = (const float*)d_in[17];
    const float* Wf2   = (const float*)d_in[18];
    const float* bf2   = (const float*)d_in[19];
    const float* lnf_g = (const float*)d_in[20];
    const float* lnf_b = (const float*)d_in[21];
    const float* headw = (const float*)d_in[22];
    float* out = (float*)d_out;

    float *ph, *pxn, *pq, *pk, *pv, *py, *pff;
    cudaGetSymbolAddress((void**)&ph,  g_h);
    cudaGetSymbolAddress((void**)&pxn, g_xn);
    cudaGetSymbolAddress((void**)&pq,  g_q);
    cudaGetSymbolAddress((void**)&pk,  g_k);
    cudaGetSymbolAddress((void**)&pv,  g_v);
    cudaGetSymbolAddress((void**)&py,  g_y);
    cudaGetSymbolAddress((void**)&pff, g_ff);

    embed_kernel<<<(BT*E + 255)/256, 256>>>(x, tok, pos, ph);

    dim3 gE (E/128,  BT/128);   // 8 x 32
    dim3 gF (FF/128, BT/128);   // 32 x 32
    dim3 gV (VOCAB/128, BT/128);
    dim3 gAtt(T/64, BATCH*H);

    for (int l = 0; l < LNUM; l++) {
        const size_t wOff = (size_t)l * E * E;
        ln_kernel<<<BT, 256>>>(ph, pxn, ln1_g + l*E, ln1_b + l*E);
        gemm128<EPI_BIAS><<<gE, 256>>>(BT, E, E, pxn, Wq + wOff, bq + l*E, nullptr, pq);
        gemm128<EPI_BIAS><<<gE, 256>>>(BT, E, E, pxn, Wk + wOff, bk + l*E, nullptr, pk);
        gemm128<EPI_BIAS><<<gE, 256>>>(BT, E, E, pxn, Wv + wOff, bv + l*E, nullptr, pv);
        attn_kernel<<<gAtt, 256>>>(pq, pk, pv, py);
        gemm128<EPI_RES ><<<gE, 256>>>(BT, E, E, py, Wp + wOff, bp + l*E, ph, ph);
        ln_kernel<<<BT, 256>>>(ph, pxn, ln2_g + l*E, ln2_b + l*E);
        gemm128<EPI_GELU><<<gF, 256>>>(BT, FF, E, pxn, Wf1 + (size_t)l*E*FF, bf1 + (size_t)l*FF, nullptr, pff);
        gemm128<EPI_RES ><<<gE, 256>>>(BT, E, FF, pff, Wf2 + (size_t)l*FF*E, bf2 + l*E, ph, ph);
    }

    ln_kernel<<<BT, 256>>>(ph, pxn, lnf_g, lnf_b);
    gemm128<EPI_BIAS><<<gV, 256>>>(BT, VOCAB, E, pxn, headw, nullptr, nullptr, out);
}

// round 4
// speedup vs baseline: 2.3511x; 2.3511x over previous
#include <cuda_runtime.h>
#include <cuda_bf16.h>
#include <math.h>
#include <stdint.h>

// ---------------- problem constants ----------------
#define LNUM 12
#define E 1024
#define H 16
#define T 512
#define BATCH 8
#define VOCAB 512
#define FF 4096
#define D 64
#define BT (BATCH*T)   // 4096

// ---------------- persistent device scratch ----------------
__device__ float g_h [BT*E];
__device__ float g_xn[BT*E];
__device__ float g_q [BT*E];
__device__ float g_k [BT*E];
__device__ float g_v [BT*E];
__device__ float g_y [BT*E];
__device__ float g_ff[(size_t)BT*FF];
// transposed (K-major) weights, tf32-rounded
__device__ float g_WqT [(size_t)LNUM*E*E];
__device__ float g_WkT [(size_t)LNUM*E*E];
__device__ float g_WvT [(size_t)LNUM*E*E];
__device__ float g_WpT [(size_t)LNUM*E*E];
__device__ float g_Wf1T[(size_t)LNUM*E*FF];
__device__ float g_Wf2T[(size_t)LNUM*FF*E];
__device__ float g_headT[(size_t)E*VOCAB];

// ---------------- helpers ----------------
__device__ __forceinline__ uint32_t smem_u32(const void* p) {
    uint32_t a;
    asm("{ .reg .u64 t; cvta.to.shared.u64 t, %1; cvt.u32.u64 %0, t; }" : "=r"(a) : "l"(p));
    return a;
}
__device__ __forceinline__ float to_tf32(float x) {
    uint32_t r; asm("cvt.rn.tf32.f32 %0, %1;" : "=r"(r) : "f"(x));
    return __uint_as_float(r);
}
__device__ __forceinline__ void cp16(uint32_t saddr, const void* g) {
    asm volatile("cp.async.cg.shared.global [%0], [%1], 16;" :: "r"(saddr), "l"(g));
}
__device__ __forceinline__ void cp_commit() {
    asm volatile("cp.async.commit_group;" ::: "memory");
}
template<int N>
__device__ __forceinline__ void cp_wait() {
    asm volatile("cp.async.wait_group %0;" :: "n"(N) : "memory");
}
__device__ __forceinline__ void mma_tf32(float* d, const float* a, float b0, float b1) {
    asm volatile("mma.sync.aligned.m16n8k8.row.col.f32.tf32.tf32.f32 "
        "{%0,%1,%2,%3}, {%4,%5,%6,%7}, {%8,%9}, {%0,%1,%2,%3};"
        : "+f"(d[0]), "+f"(d[1]), "+f"(d[2]), "+f"(d[3])
        : "r"(__float_as_uint(a[0])), "r"(__float_as_uint(a[1])),
          "r"(__float_as_uint(a[2])), "r"(__float_as_uint(a[3])),
          "r"(__float_as_uint(b0)),  "r"(__float_as_uint(b1)));
}

// ---------------- embedding ----------------
__global__ void embed_kernel(const int* __restrict__ x,
                             const float* __restrict__ tok,
                             const float* __restrict__ pos,
                             float* __restrict__ h)
{
    int idx = blockIdx.x * blockDim.x + threadIdx.x;
    if (idx >= BT*E) return;
    int row = idx >> 10;
    int e   = idx & (E-1);
    int t   = row & (T-1);
    h[idx] = tok[(size_t)x[row]*E + e] + pos[(size_t)t*E + e];
}

// ---------------- layernorm (output tf32-rounded: feeds GEMM A) ----------------
__global__ __launch_bounds__(256) void ln_kernel(const float* __restrict__ in,
                                                 float* __restrict__ out,
                                                 const float* __restrict__ gamma,
                                                 const float* __restrict__ beta)
{
    int row = blockIdx.x;
    const float* xr = in + (size_t)row * E;
    float s = 0.f, ss = 0.f;
    for (int i = threadIdx.x; i < E; i += 256) {
        float v = xr[i]; s += v; ss += v * v;
    }
    #pragma unroll
    for (int o = 16; o > 0; o >>= 1) {
        s  += __shfl_xor_sync(0xffffffffu, s,  o);
        ss += __shfl_xor_sync(0xffffffffu, ss, o);
    }
    __shared__ float sred[8], ssred[8];
    int w = threadIdx.x >> 5;
    if ((threadIdx.x & 31) == 0) { sred[w] = s; ssred[w] = ss; }
    __syncthreads();
    if (threadIdx.x < 32) {
        s  = (threadIdx.x < 8) ? sred [threadIdx.x] : 0.f;
        ss = (threadIdx.x < 8) ? ssred[threadIdx.x] : 0.f;
        #pragma unroll
        for (int o = 4; o > 0; o >>= 1) {
            s  += __shfl_xor_sync(0xffffffffu, s,  o);
            ss += __shfl_xor_sync(0xffffffffu, ss, o);
        }
        if (threadIdx.x == 0) { sred[0] = s; ssred[0] = ss; }
    }
    __syncthreads();
    float mu   = sred[0] * (1.f / E);
    float var  = ssred[0] * (1.f / E) - mu * mu;
    float rstd = rsqrtf(var + 1e-5f);
    float* orow = out + (size_t)row * E;
    for (int i = threadIdx.x; i < E; i += 256)
        orow[i] = to_tf32((xr[i] - mu) * rstd * gamma[i] + beta[i]);
}

// ---------------- weight transpose ([R,C] -> [C,R], tf32-rounded) ----------------
__global__ __launch_bounds__(256) void transpose_tf32(const float* __restrict__ in,
                                                      float* __restrict__ out, int R, int C)
{
    __shared__ float tile[32][33];
    size_t mat = (size_t)blockIdx.z * R * C;
    int c0 = blockIdx.x * 32, r0 = blockIdx.y * 32;
    #pragma unroll
    for (int j = threadIdx.y; j < 32; j += 8)
        tile[j][threadIdx.x] = in[mat + (size_t)(r0 + j) * C + c0 + threadIdx.x];
    __syncthreads();
    #pragma unroll
    for (int j = threadIdx.y; j < 32; j += 8)
        out[mat + (size_t)(c0 + j) * R + r0 + threadIdx.x] = to_tf32(tile[threadIdx.x][j]);
}

// ---------------- mma.sync tf32 GEMM ----------------
// C[M,N] = A[M,K] @ Bt[N,K]^T (+bias)(+epilogue).
// Block tile 128x128, 8 warps (4 m x 2 n), warp tile 32x64, K-tile 32.
// A and Bt must already be tf32-rounded. smem rows padded to 36 floats
// => fragment-load bank = (4*r + c) mod 32, conflict-free.
#define EPI_BIAS 0
#define EPI_GELU 1
#define EPI_RES  2
#define TKm 32
#define TILE_F   (128*36)            // floats per tile
#define TILE_B   (TILE_F*4)          // 18432 bytes
#define GSM_BYTES (4*TILE_B)         // 73728 bytes

template<int EPI>
__global__ __launch_bounds__(256) void gemm_mma(int M, int N, int K,
    const float* __restrict__ A, const float* __restrict__ Bt,
    const float* __restrict__ bias, const float* __restrict__ res,
    float* __restrict__ C)
{
    extern __shared__ float smem[];
    const uint32_t sbase = smem_u32(smem);
    const int tid  = threadIdx.x;
    const int wid  = tid >> 5, lane = tid & 31;
    const int wm   = wid & 3, wn = wid >> 2;
    const int g    = lane >> 2, c = lane & 3;

    const size_t m0 = (size_t)blockIdx.y * 128;
    const int    n0 = blockIdx.x * 128;
    const int    nK = K / TKm;

    // offsets (bytes): As0, As1, Bs0, Bs1
    const uint32_t sA[2] = { sbase,              sbase + TILE_B };
    const uint32_t sB[2] = { sbase + 2*TILE_B,   sbase + 3*TILE_B };

    // global->shared tile loaders (128 rows x 32 k, 16B chunks)
    auto load_tiles = [&](int kt, int st) {
        const int k0 = kt * TKm;
        #pragma unroll
        for (int i = 0; i < 4; i++) {
            int idx = i*256 + tid;
            int row = idx >> 3, kq = idx & 7;
            cp16(sA[st] + row*144 + kq*16, A  + (m0 + row) * K + k0 + kq*4);
            cp16(sB[st] + row*144 + kq*16, Bt + (size_t)(n0 + row) * K + k0 + kq*4);
        }
        cp_commit();
    };

    float acc[2][8][4];
    #pragma unroll
    for (int mf = 0; mf < 2; mf++)
        #pragma unroll
        for (int nf = 0; nf < 8; nf++)
            #pragma unroll
            for (int i = 0; i < 4; i++) acc[mf][nf][i] = 0.f;

    load_tiles(0, 0);

    for (int kt = 0; kt < nK; kt++) {
        const int st = kt & 1;
        if (kt + 1 < nK) { load_tiles(kt + 1, st ^ 1); cp_wait<1>(); }
        else             { cp_wait<0>(); }
        __syncthreads();

        const float* as = (const float*)smem + st*TILE_F;
        const float* bs = (const float*)smem + (2 + st)*TILE_F;
        #pragma unroll
        for (int ks = 0; ks < 4; ks++) {
            const int kb = ks * 8;
            float a[2][4];
            #pragma unroll
            for (int mf = 0; mf < 2; mf++) {
                int r = wm*32 + mf*16 + g;
                a[mf][0] = as[ r     *36 + kb + c    ];
                a[mf][1] = as[(r + 8)*36 + kb + c    ];
                a[mf][2] = as[ r     *36 + kb + c + 4];
                a[mf][3] = as[(r + 8)*36 + kb + c + 4];
            }
            #pragma unroll
            for (int nf = 0; nf < 8; nf++) {
                int n = wn*64 + nf*8 + g;
                float b0 = bs[n*36 + kb + c];
                float b1 = bs[n*36 + kb + c + 4];
                mma_tf32(acc[0][nf], a[0], b0, b1);
                mma_tf32(acc[1][nf], a[1], b0, b1);
            }
        }
        __syncthreads();
    }

    // epilogue: direct register -> global
    #pragma unroll
    for (int mf = 0; mf < 2; mf++) {
        size_t r = m0 + wm*32 + mf*16 + g;
        #pragma unroll
        for (int nf = 0; nf < 8; nf++) {
            int col = n0 + wn*64 + nf*8 + c*2;
            float v0 = acc[mf][nf][0], v1 = acc[mf][nf][1];
            float v2 = acc[mf][nf][2], v3 = acc[mf][nf][3];
            if (bias) {
                float bb0 = bias[col], bb1 = bias[col+1];
                v0 += bb0; v1 += bb1; v2 += bb0; v3 += bb1;
            }
            if (EPI == EPI_GELU) {
                v0 = to_tf32(0.5f*v0*(1.f + erff(v0*0.70710678118654752f)));
                v1 = to_tf32(0.5f*v1*(1.f + erff(v1*0.70710678118654752f)));
                v2 = to_tf32(0.5f*v2*(1.f + erff(v2*0.70710678118654752f)));
                v3 = to_tf32(0.5f*v3*(1.f + erff(v3*0.70710678118654752f)));
            }
            if (EPI == EPI_RES) {
                float2 r0 = *(const float2*)(res + r*N + col);
                float2 r1 = *(const float2*)(res + (r+8)*N + col);
                v0 += r0.x; v1 += r0.y; v2 += r1.x; v3 += r1.y;
            }
            float2 o0 = {v0, v1}, o1 = {v2, v3};
            *(float2*)(C + r*N + col)     = o0;
            *(float2*)(C + (r+8)*N + col) = o1;
        }
    }
}

// ---------------- fused causal attention (flash-style, fp32) ----------------
// Output rounded to tf32 (feeds proj GEMM A).
__global__ __launch_bounds__(256) void attn_kernel(const float* __restrict__ Q,
                                                   const float* __restrict__ K,
                                                   const float* __restrict__ V,
                                                   float* __restrict__ Y)
{
    int bh = blockIdx.y;
    int b  = bh >> 4;
    int h  = bh & 15;
    int qt = blockIdx.x;
    int tid = threadIdx.x;
    int r  = tid >> 2;
    int c4 = tid & 3;

    __shared__ float sK[64][D];
    __shared__ float sV[64][D];

    int qrow = qt * 64 + r;
    const float* qp = Q + ((size_t)(b*T + qrow)) * E + h*D + c4*16;
    float qreg[16];
    #pragma unroll
    for (int i = 0; i < 16; i++) qreg[i] = qp[i] * 0.125f;

    float acc[16];
    #pragma unroll
    for (int i = 0; i < 16; i++) acc[i] = 0.f;
    float mcur = -INFINITY, l = 0.f;

    for (int kt = 0; kt <= qt; kt++) {
        __syncthreads();
        #pragma unroll 4
        for (int i = tid; i < 64*64; i += 256) {
            int kr = i >> 6, kc = i & 63;
            size_t gg = ((size_t)(b*T + kt*64 + kr)) * E + h*D + kc;
            sK[kr][kc] = K[gg];
            sV[kr][kc] = V[gg];
        }
        __syncthreads();

        float s[64];
        #pragma unroll
        for (int k = 0; k < 64; k++) {
            float d = 0.f;
            #pragma unroll
            for (int i = 0; i < 16; i++)
                d = fmaf(qreg[i], sK[k][c4*16 + i], d);
            d += __shfl_xor_sync(0xffffffffu, d, 1);
            d += __shfl_xor_sync(0xffffffffu, d, 2);
            s[k] = d;
        }
        if (kt == qt) {
            #pragma unroll
            for (int k = 0; k < 64; k++)
                if (kt*64 + k > qrow) s[k] = -INFINITY;
        }
        float tmax = mcur;
        #pragma unroll
        for (int k = 0; k < 64; k++) tmax = fmaxf(tmax, s[k]);
        float fac = __expf(mcur - tmax);
        mcur = tmax;
        l *= fac;
        #pragma unroll
        for (int i = 0; i < 16; i++) acc[i] *= fac;
        #pragma unroll
        for (int k = 0; k < 64; k++) {
            float p = __expf(s[k] - mcur);
            l += p;
            #pragma unroll
            for (int i = 0; i < 16; i++)
                acc[i] = fmaf(p, sV[k][c4*16 + i], acc[i]);
        }
    }

    float inv = 1.f / l;
    float* yp = Y + ((size_t)(b*T + qrow)) * E + h*D + c4*16;
    #pragma unroll
    for (int i = 0; i < 16; i++) yp[i] = to_tf32(acc[i] * inv);
}

// ---------------- host orchestration ----------------
extern "C" void kernel_launch(void* const* d_in, const int* in_sizes, int n_in,
                              void* d_out, int out_size)
{
    (void)in_sizes; (void)n_in; (void)out_size;
    const int*   x     = (const int*)  d_in[0];
    const float* tok   = (const float*)d_in[2];
    const float* pos   = (const float*)d_in[3];
    const float* ln1_g = (const float*)d_in[4];
    const float* ln1_b = (const float*)d_in[5];
    const float* Wq    = (const float*)d_in[6];
    const float* bq    = (const float*)d_in[7];
    const float* Wk    = (const float*)d_in[8];
    const float* bk    = (const float*)d_in[9];
    const float* Wv    = (const float*)d_in[10];
    const float* bv    = (const float*)d_in[11];
    const float* Wp    = (const float*)d_in[12];
    const float* bp    = (const float*)d_in[13];
    const float* ln2_g = (const float*)d_in[14];
    const float* ln2_b = (const float*)d_in[15];
    const float* Wf1   = (const float*)d_in[16];
    const float* bf1   = (const float*)d_in[17];
    const float* Wf2   = (const float*)d_in[18];
    const float* bf2   = (const float*)d_in[19];
    const float* lnf_g = (const float*)d_in[20];
    const float* lnf_b = (const float*)d_in[21];
    const float* headw = (const float*)d_in[22];
    float* out = (float*)d_out;

    float *ph, *pxn, *pq, *pk, *pv, *py, *pff;
    float *pWqT, *pWkT, *pWvT, *pWpT, *pWf1T, *pWf2T, *pHT;
    cudaGetSymbolAddress((void**)&ph,   g_h);
    cudaGetSymbolAddress((void**)&pxn,  g_xn);
    cudaGetSymbolAddress((void**)&pq,   g_q);
    cudaGetSymbolAddress((void**)&pk,   g_k);
    cudaGetSymbolAddress((void**)&pv,   g_v);
    cudaGetSymbolAddress((void**)&py,   g_y);
    cudaGetSymbolAddress((void**)&pff,  g_ff);
    cudaGetSymbolAddress((void**)&pWqT, g_WqT);
    cudaGetSymbolAddress((void**)&pWkT, g_WkT);
    cudaGetSymbolAddress((void**)&pWvT, g_WvT);
    cudaGetSymbolAddress((void**)&pWpT, g_WpT);
    cudaGetSymbolAddress((void**)&pWf1T, g_Wf1T);
    cudaGetSymbolAddress((void**)&pWf2T, g_Wf2T);
    cudaGetSymbolAddress((void**)&pHT,  g_headT);

    cudaFuncSetAttribute(gemm_mma<EPI_BIAS>, cudaFuncAttributeMaxDynamicSharedMemorySize, GSM_BYTES);
    cudaFuncSetAttribute(gemm_mma<EPI_GELU>, cudaFuncAttributeMaxDynamicSharedMemorySize, GSM_BYTES);
    cudaFuncSetAttribute(gemm_mma<EPI_RES >, cudaFuncAttributeMaxDynamicSharedMemorySize, GSM_BYTES);

    // weight transposes (K-major B operand), tf32-rounded
    dim3 tb(32, 8);
    transpose_tf32<<<dim3(E/32,  E/32,  LNUM), tb>>>(Wq,  pWqT,  E,  E);
    transpose_tf32<<<dim3(E/32,  E/32,  LNUM), tb>>>(Wk,  pWkT,  E,  E);
    transpose_tf32<<<dim3(E/32,  E/32,  LNUM), tb>>>(Wv,  pWvT,  E,  E);
    transpose_tf32<<<dim3(E/32,  E/32,  LNUM), tb>>>(Wp,  pWpT,  E,  E);
    transpose_tf32<<<dim3(FF/32, E/32,  LNUM), tb>>>(Wf1, pWf1T, E,  FF);
    transpose_tf32<<<dim3(E/32,  FF/32, LNUM), tb>>>(Wf2, pWf2T, FF, E);
    transpose_tf32<<<dim3(VOCAB/32, E/32, 1),  tb>>>(headw, pHT, E,  VOCAB);

    embed_kernel<<<(BT*E + 255)/256, 256>>>(x, tok, pos, ph);

    dim3 gE(E/128,     BT/128);   // (8,32)
    dim3 gF(FF/128,    BT/128);   // (32,32)
    dim3 gV(VOCAB/128, BT/128);   // (4,32)
    dim3 gAtt(T/64, BATCH*H);

    for (int l = 0; l < LNUM; l++) {
        const size_t wOff  = (size_t)l * E * E;
        const size_t f1Off = (size_t)l * E * FF;
        ln_kernel<<<BT, 256>>>(ph, pxn, ln1_g + l*E, ln1_b + l*E);
        gemm_mma<EPI_BIAS><<<gE, 256, GSM_BYTES>>>(BT, E, E, pxn, pWqT + wOff, bq + l*E, nullptr, pq);
        gemm_mma<EPI_BIAS><<<gE, 256, GSM_BYTES>>>(BT, E, E, pxn, pWkT + wOff, bk + l*E, nullptr, pk);
        gemm_mma<EPI_BIAS><<<gE, 256, GSM_BYTES>>>(BT, E, E, pxn, pWvT + wOff, bv + l*E, nullptr, pv);
        attn_kernel<<<gAtt, 256>>>(pq, pk, pv, py);
        gemm_mma<EPI_RES ><<<gE, 256, GSM_BYTES>>>(BT, E, E, py, pWpT + wOff, bp + l*E, ph, ph);
        ln_kernel<<<BT, 256>>>(ph, pxn, ln2_g + l*E, ln2_b + l*E);
        gemm_mma<EPI_GELU><<<gF, 256, GSM_BYTES>>>(BT, FF, E, pxn, pWf1T + f1Off, bf1 + (size_t)l*FF, nullptr, pff);
        gemm_mma<EPI_RES ><<<gE, 256, GSM_BYTES>>>(BT, E, FF, pff, pWf2T + f1Off, bf2 + l*E, ph, ph);
    }

    ln_kernel<<<BT, 256>>>(ph, pxn, lnf_g, lnf_b);
    gemm_mma<EPI_BIAS><<<gV, 256, GSM_BYTES>>>(BT, VOCAB, E, pxn, pHT, nullptr, nullptr, out);
}

// round 5
// speedup vs baseline: 2.3878x; 1.0156x over previous
#include <cuda_runtime.h>
#include <cuda_bf16.h>
#include <math.h>
#include <stdint.h>

// ---------------- problem constants ----------------
#define LNUM 12
#define E 1024
#define H 16
#define T 512
#define BATCH 8
#define VOCAB 512
#define FF 4096
#define D 64
#define BT (BATCH*T)   // 4096

// ---------------- persistent device scratch ----------------
__device__ float g_h [BT*E];
__device__ float g_xn[BT*E];     // k-permuted
__device__ float g_q [BT*E];
__device__ float g_k [BT*E];
__device__ float g_v [BT*E];
__device__ float g_y [BT*E];     // k-permuted
__device__ float g_ff[(size_t)BT*FF];  // k-permuted
// transposed (K-major, k-permuted) weights, tf32-rounded
__device__ float g_WqT [(size_t)LNUM*E*E];
__device__ float g_WkT [(size_t)LNUM*E*E];
__device__ float g_WvT [(size_t)LNUM*E*E];
__device__ float g_WpT [(size_t)LNUM*E*E];
__device__ float g_Wf1T[(size_t)LNUM*E*FF];
__device__ float g_Wf2T[(size_t)LNUM*FF*E];
__device__ float g_headT[(size_t)E*VOCAB];

// ---------------- helpers ----------------
__device__ __forceinline__ uint32_t smem_u32(const void* p) {
    uint32_t a;
    asm("{ .reg .u64 t; cvta.to.shared.u64 t, %1; cvt.u32.u64 %0, t; }" : "=r"(a) : "l"(p));
    return a;
}
__device__ __forceinline__ float to_tf32(float x) {
    uint32_t r; asm("cvt.rn.tf32.f32 %0, %1;" : "=r"(r) : "f"(x));
    return __uint_as_float(r);
}
__device__ __forceinline__ void cp16(uint32_t saddr, const void* g) {
    asm volatile("cp.async.cg.shared.global [%0], [%1], 16;" :: "r"(saddr), "l"(g));
}
__device__ __forceinline__ void cp_commit() {
    asm volatile("cp.async.commit_group;" ::: "memory");
}
template<int N>
__device__ __forceinline__ void cp_wait() {
    asm volatile("cp.async.wait_group %0;" :: "n"(N) : "memory");
}
__device__ __forceinline__ void mma_tf32(float* d, float a0, float a1, float a2, float a3,
                                         float b0, float b1) {
    asm volatile("mma.sync.aligned.m16n8k8.row.col.f32.tf32.tf32.f32 "
        "{%0,%1,%2,%3}, {%4,%5,%6,%7}, {%8,%9}, {%0,%1,%2,%3};"
        : "+f"(d[0]), "+f"(d[1]), "+f"(d[2]), "+f"(d[3])
        : "r"(__float_as_uint(a0)), "r"(__float_as_uint(a1)),
          "r"(__float_as_uint(a2)), "r"(__float_as_uint(a3)),
          "r"(__float_as_uint(b0)), "r"(__float_as_uint(b1)));
}
// permute within each 8-block: logical k -> physical pos (0,4,1,5,2,6,3,7)
__device__ __forceinline__ int perm8(int i) {
    return (i & ~7) | ((i & 3) << 1) | ((i >> 2) & 1);
}

// ---------------- embedding ----------------
__global__ void embed_kernel(const int* __restrict__ x,
                             const float* __restrict__ tok,
                             const float* __restrict__ pos,
                             float* __restrict__ h)
{
    int idx = blockIdx.x * blockDim.x + threadIdx.x;
    if (idx >= BT*E) return;
    int row = idx >> 10;
    int e   = idx & (E-1);
    int t   = row & (T-1);
    h[idx] = tok[(size_t)x[row]*E + e] + pos[(size_t)t*E + e];
}

// ---------------- layernorm (tf32-rounded, k-permuted output) ----------------
__global__ __launch_bounds__(256) void ln_kernel(const float* __restrict__ in,
                                                 float* __restrict__ out,
                                                 const float* __restrict__ gamma,
                                                 const float* __restrict__ beta)
{
    int row = blockIdx.x;
    const float* xr = in + (size_t)row * E;
    float s = 0.f, ss = 0.f;
    for (int i = threadIdx.x; i < E; i += 256) {
        float v = xr[i]; s += v; ss += v * v;
    }
    #pragma unroll
    for (int o = 16; o > 0; o >>= 1) {
        s  += __shfl_xor_sync(0xffffffffu, s,  o);
        ss += __shfl_xor_sync(0xffffffffu, ss, o);
    }
    __shared__ float sred[8], ssred[8];
    int w = threadIdx.x >> 5;
    if ((threadIdx.x & 31) == 0) { sred[w] = s; ssred[w] = ss; }
    __syncthreads();
    if (threadIdx.x < 32) {
        s  = (threadIdx.x < 8) ? sred [threadIdx.x] : 0.f;
        ss = (threadIdx.x < 8) ? ssred[threadIdx.x] : 0.f;
        #pragma unroll
        for (int o = 4; o > 0; o >>= 1) {
            s  += __shfl_xor_sync(0xffffffffu, s,  o);
            ss += __shfl_xor_sync(0xffffffffu, ss, o);
        }
        if (threadIdx.x == 0) { sred[0] = s; ssred[0] = ss; }
    }
    __syncthreads();
    float mu   = sred[0] * (1.f / E);
    float var  = ssred[0] * (1.f / E) - mu * mu;
    float rstd = rsqrtf(var + 1e-5f);
    float* orow = out + (size_t)row * E;
    for (int i = threadIdx.x; i < E; i += 256)
        orow[perm8(i)] = to_tf32((xr[i] - mu) * rstd * gamma[i] + beta[i]);
}

// ---------------- weight transpose ([R,C] -> [C,R], tf32, k-permuted) ----------------
__global__ __launch_bounds__(256) void transpose_tf32(const float* __restrict__ in,
                                                      float* __restrict__ out, int R, int C)
{
    __shared__ float tile[32][33];
    size_t mat = (size_t)blockIdx.z * R * C;
    int c0 = blockIdx.x * 32, r0 = blockIdx.y * 32;
    #pragma unroll
    for (int j = threadIdx.y; j < 32; j += 8)
        tile[j][threadIdx.x] = in[mat + (size_t)(r0 + j) * C + c0 + threadIdx.x];
    __syncthreads();
    int ptx = perm8((int)threadIdx.x);
    #pragma unroll
    for (int j = threadIdx.y; j < 32; j += 8)
        out[mat + (size_t)(c0 + j) * R + r0 + ptx] = to_tf32(tile[threadIdx.x][j]);
}

// ---------------- mma.sync tf32 GEMM (256x128 tile, 8 warps 64x64) ----------------
// C[M,N] = A[M,K] @ Bt[N,K]^T (+bias)(+epilogue).
// A, Bt in k-permuted tf32 layout. smem rows: 32 k-words padded to 40 (160B).
#define EPI_BIAS 0
#define EPI_GELU 1
#define EPI_RES  2
#define TKm 32
#define ROWW 40                       // words per smem row
#define STG_AF (256*ROWW)             // A floats/stage = 10240
#define STG_BF (128*ROWW)             // B floats/stage = 5120
#define STG_F  (STG_AF+STG_BF)        // 15360 floats
#define STG_B  (STG_F*4)              // 61440 bytes
#define GSM_BYTES (3*STG_B)           // 184320 bytes

template<int EPI, int PERM>
__global__ __launch_bounds__(256) void gemm_mma(int M, int N, int K,
    const float* __restrict__ A, const float* __restrict__ Bt,
    const float* __restrict__ bias, const float* __restrict__ res,
    float* __restrict__ C)
{
    extern __shared__ float smem[];
    const uint32_t sbase = smem_u32(smem);
    const int tid  = threadIdx.x;
    const int wid  = tid >> 5, lane = tid & 31;
    const int wm   = wid & 3, wn = wid >> 2;      // 4 x 2 warps, 64x64 each
    const int g    = lane >> 2, c = lane & 3;

    const size_t m0 = (size_t)blockIdx.y * 256;
    const int    n0 = blockIdx.x * 128;
    const int    nK = K / TKm;

    const int ldrow = tid >> 3, ldch = tid & 7;   // loader mapping

    auto load_tiles = [&](int kt, int st) {
        const int k0 = kt * TKm;
        const uint32_t sA = sbase + st*STG_B;
        const uint32_t sB = sA + STG_AF*4;
        const float* Ag = A  + (m0 + ldrow) * K + k0 + ldch*4;
        #pragma unroll
        for (int i = 0; i < 8; i++)
            cp16(sA + (ldrow + i*32)*160 + ldch*16, Ag + (size_t)(i*32) * K);
        const float* Bg = Bt + (size_t)(n0 + ldrow) * K + k0 + ldch*4;
        #pragma unroll
        for (int i = 0; i < 4; i++)
            cp16(sB + (ldrow + i*32)*160 + ldch*16, Bg + (size_t)(i*32) * K);
        cp_commit();
    };

    float acc[4][8][4];
    #pragma unroll
    for (int mf = 0; mf < 4; mf++)
        #pragma unroll
        for (int nf = 0; nf < 8; nf++)
            #pragma unroll
            for (int i = 0; i < 4; i++) acc[mf][nf][i] = 0.f;

    load_tiles(0, 0);
    load_tiles(1, 1);

    for (int kt = 0; kt < nK; kt++) {
        const int st = kt % 3;
        if (kt < nK - 1) cp_wait<1>(); else cp_wait<0>();
        __syncthreads();
        if (kt + 2 < nK) load_tiles(kt + 2, (kt + 2) % 3);

        const float* as = smem + st*STG_F;
        const float* bs = as + STG_AF;
        #pragma unroll
        for (int ks = 0; ks < 4; ks++) {
            const int kw = ks*8 + 2*c;
            float2 af[4][2];
            #pragma unroll
            for (int mf = 0; mf < 4; mf++) {
                int r = wm*64 + mf*16 + g;
                af[mf][0] = *(const float2*)&as[ r      * ROWW + kw];
                af[mf][1] = *(const float2*)&as[(r + 8) * ROWW + kw];
            }
            float2 bf[8];
            #pragma unroll
            for (int nf = 0; nf < 8; nf++)
                bf[nf] = *(const float2*)&bs[(wn*64 + nf*8 + g) * ROWW + kw];
            #pragma unroll
            for (int mf = 0; mf < 4; mf++)
                #pragma unroll
                for (int nf = 0; nf < 8; nf++)
                    mma_tf32(acc[mf][nf],
                             af[mf][0].x, af[mf][1].x, af[mf][0].y, af[mf][1].y,
                             bf[nf].x, bf[nf].y);
        }
        __syncthreads();
    }

    // epilogue
    #pragma unroll
    for (int mf = 0; mf < 4; mf++) {
        size_t r = m0 + wm*64 + mf*16 + g;
        #pragma unroll
        for (int nf = 0; nf < 8; nf++) {
            int col = n0 + wn*64 + nf*8 + c*2;
            float v0 = acc[mf][nf][0], v1 = acc[mf][nf][1];
            float v2 = acc[mf][nf][2], v3 = acc[mf][nf][3];
            if (bias) {
                float bb0 = bias[col], bb1 = bias[col+1];
                v0 += bb0; v1 += bb1; v2 += bb0; v3 += bb1;
            }
            if (EPI == EPI_GELU) {
                v0 = to_tf32(0.5f*v0*(1.f + erff(v0*0.70710678118654752f)));
                v1 = to_tf32(0.5f*v1*(1.f + erff(v1*0.70710678118654752f)));
                v2 = to_tf32(0.5f*v2*(1.f + erff(v2*0.70710678118654752f)));
                v3 = to_tf32(0.5f*v3*(1.f + erff(v3*0.70710678118654752f)));
            }
            if (EPI == EPI_RES) {
                float2 r0 = *(const float2*)(res + r*N + col);
                float2 r1 = *(const float2*)(res + (r+8)*N + col);
                v0 += r0.x; v1 += r0.y; v2 += r1.x; v3 += r1.y;
            }
            if (PERM) {
                int p0 = perm8(col), p1 = perm8(col + 1);
                C[r*N + p0]     = v0;  C[r*N + p1]     = v1;
                C[(r+8)*N + p0] = v2;  C[(r+8)*N + p1] = v3;
            } else {
                float2 o0 = {v0, v1}, o1 = {v2, v3};
                *(float2*)(C + r*N + col)     = o0;
                *(float2*)(C + (r+8)*N + col) = o1;
            }
        }
    }
}

// ---------------- fused causal attention (fp32; tf32-rounded, k-permuted output) ----
__global__ __launch_bounds__(256) void attn_kernel(const float* __restrict__ Q,
                                                   const float* __restrict__ K,
                                                   const float* __restrict__ V,
                                                   float* __restrict__ Y)
{
    int bh = blockIdx.y;
    int b  = bh >> 4;
    int h  = bh & 15;
    int qt = blockIdx.x;
    int tid = threadIdx.x;
    int r  = tid >> 2;
    int c4 = tid & 3;

    __shared__ float sK[64][D];
    __shared__ float sV[64][D];

    int qrow = qt * 64 + r;
    const float* qp = Q + ((size_t)(b*T + qrow)) * E + h*D + c4*16;
    float qreg[16];
    #pragma unroll
    for (int i = 0; i < 16; i++) qreg[i] = qp[i] * 0.125f;

    float acc[16];
    #pragma unroll
    for (int i = 0; i < 16; i++) acc[i] = 0.f;
    float mcur = -INFINITY, l = 0.f;

    for (int kt = 0; kt <= qt; kt++) {
        __syncthreads();
        #pragma unroll 4
        for (int i = tid; i < 64*64; i += 256) {
            int kr = i >> 6, kc = i & 63;
            size_t gg = ((size_t)(b*T + kt*64 + kr)) * E + h*D + kc;
            sK[kr][kc] = K[gg];
            sV[kr][kc] = V[gg];
        }
        __syncthreads();

        float s[64];
        #pragma unroll
        for (int k = 0; k < 64; k++) {
            float d = 0.f;
            #pragma unroll
            for (int i = 0; i < 16; i++)
                d = fmaf(qreg[i], sK[k][c4*16 + i], d);
            d += __shfl_xor_sync(0xffffffffu, d, 1);
            d += __shfl_xor_sync(0xffffffffu, d, 2);
            s[k] = d;
        }
        if (kt == qt) {
            #pragma unroll
            for (int k = 0; k < 64; k++)
                if (kt*64 + k > qrow) s[k] = -INFINITY;
        }
        float tmax = mcur;
        #pragma unroll
        for (int k = 0; k < 64; k++) tmax = fmaxf(tmax, s[k]);
        float fac = __expf(mcur - tmax);
        mcur = tmax;
        l *= fac;
        #pragma unroll
        for (int i = 0; i < 16; i++) acc[i] *= fac;
        #pragma unroll
        for (int k = 0; k < 64; k++) {
            float p = __expf(s[k] - mcur);
            l += p;
            #pragma unroll
            for (int i = 0; i < 16; i++)
                acc[i] = fmaf(p, sV[k][c4*16 + i], acc[i]);
        }
    }

    float inv = 1.f / l;
    float* yrow = Y + ((size_t)(b*T + qrow)) * E;
    int colbase = h*D + c4*16;
    #pragma unroll
    for (int i = 0; i < 16; i++)
        yrow[perm8(colbase + i)] = to_tf32(acc[i] * inv);
}

// ---------------- host orchestration ----------------
extern "C" void kernel_launch(void* const* d_in, const int* in_sizes, int n_in,
                              void* d_out, int out_size)
{
    (void)in_sizes; (void)n_in; (void)out_size;
    const int*   x     = (const int*)  d_in[0];
    const float* tok   = (const float*)d_in[2];
    const float* pos   = (const float*)d_in[3];
    const float* ln1_g = (const float*)d_in[4];
    const float* ln1_b = (const float*)d_in[5];
    const float* Wq    = (const float*)d_in[6];
    const float* bq    = (const float*)d_in[7];
    const float* Wk    = (const float*)d_in[8];
    const float* bk    = (const float*)d_in[9];
    const float* Wv    = (const float*)d_in[10];
    const float* bv    = (const float*)d_in[11];
    const float* Wp    = (const float*)d_in[12];
    const float* bp    = (const float*)d_in[13];
    const float* ln2_g = (const float*)d_in[14];
    const float* ln2_b = (const float*)d_in[15];
    const float* Wf1   = (const float*)d_in[16];
    const float* bf1   = (const float*)d_in[17];
    const float* Wf2   = (const float*)d_in[18];
    const float* bf2   = (const float*)d_in[19];
    const float* lnf_g = (const float*)d_in[20];
    const float* lnf_b = (const float*)d_in[21];
    const float* headw = (const float*)d_in[22];
    float* out = (float*)d_out;

    float *ph, *pxn, *pq, *pk, *pv, *py, *pff;
    float *pWqT, *pWkT, *pWvT, *pWpT, *pWf1T, *pWf2T, *pHT;
    cudaGetSymbolAddress((void**)&ph,   g_h);
    cudaGetSymbolAddress((void**)&pxn,  g_xn);
    cudaGetSymbolAddress((void**)&pq,   g_q);
    cudaGetSymbolAddress((void**)&pk,   g_k);
    cudaGetSymbolAddress((void**)&pv,   g_v);
    cudaGetSymbolAddress((void**)&py,   g_y);
    cudaGetSymbolAddress((void**)&pff,  g_ff);
    cudaGetSymbolAddress((void**)&pWqT, g_WqT);
    cudaGetSymbolAddress((void**)&pWkT, g_WkT);
    cudaGetSymbolAddress((void**)&pWvT, g_WvT);
    cudaGetSymbolAddress((void**)&pWpT, g_WpT);
    cudaGetSymbolAddress((void**)&pWf1T, g_Wf1T);
    cudaGetSymbolAddress((void**)&pWf2T, g_Wf2T);
    cudaGetSymbolAddress((void**)&pHT,  g_headT);

    cudaFuncSetAttribute(gemm_mma<EPI_BIAS,0>, cudaFuncAttributeMaxDynamicSharedMemorySize, GSM_BYTES);
    cudaFuncSetAttribute(gemm_mma<EPI_GELU,1>, cudaFuncAttributeMaxDynamicSharedMemorySize, GSM_BYTES);
    cudaFuncSetAttribute(gemm_mma<EPI_RES ,0>, cudaFuncAttributeMaxDynamicSharedMemorySize, GSM_BYTES);

    // weight transposes (K-major, k-permuted), tf32-rounded
    dim3 tb(32, 8);
    transpose_tf32<<<dim3(E/32,  E/32,  LNUM), tb>>>(Wq,  pWqT,  E,  E);
    transpose_tf32<<<dim3(E/32,  E/32,  LNUM), tb>>>(Wk,  pWkT,  E,  E);
    transpose_tf32<<<dim3(E/32,  E/32,  LNUM), tb>>>(Wv,  pWvT,  E,  E);
    transpose_tf32<<<dim3(E/32,  E/32,  LNUM), tb>>>(Wp,  pWpT,  E,  E);
    transpose_tf32<<<dim3(FF/32, E/32,  LNUM), tb>>>(Wf1, pWf1T, E,  FF);
    transpose_tf32<<<dim3(E/32,  FF/32, LNUM), tb>>>(Wf2, pWf2T, FF, E);
    transpose_tf32<<<dim3(VOCAB/32, E/32, 1),  tb>>>(headw, pHT, E,  VOCAB);

    embed_kernel<<<(BT*E + 255)/256, 256>>>(x, tok, pos, ph);

    dim3 gE(E/128,     BT/256);   // (8,16)
    dim3 gF(FF/128,    BT/256);   // (32,16)
    dim3 gV(VOCAB/128, BT/256);   // (4,16)
    dim3 gAtt(T/64, BATCH*H);

    for (int l = 0; l < LNUM; l++) {
        const size_t wOff  = (size_t)l * E * E;
        const size_t f1Off = (size_t)l * E * FF;
        ln_kernel<<<BT, 256>>>(ph, pxn, ln1_g + l*E, ln1_b + l*E);
        gemm_mma<EPI_BIAS,0><<<gE, 256, GSM_BYTES>>>(BT, E, E, pxn, pWqT + wOff, bq + l*E, nullptr, pq);
        gemm_mma<EPI_BIAS,0><<<gE, 256, GSM_BYTES>>>(BT, E, E, pxn, pWkT + wOff, bk + l*E, nullptr, pk);
        gemm_mma<EPI_BIAS,0><<<gE, 256, GSM_BYTES>>>(BT, E, E, pxn, pWvT + wOff, bv + l*E, nullptr, pv);
        attn_kernel<<<gAtt, 256>>>(pq, pk, pv, py);
        gemm_mma<EPI_RES ,0><<<gE, 256, GSM_BYTES>>>(BT, E, E, py, pWpT + wOff, bp + l*E, ph, ph);
        ln_kernel<<<BT, 256>>>(ph, pxn, ln2_g + l*E, ln2_b + l*E);
        gemm_mma<EPI_GELU,1><<<gF, 256, GSM_BYTES>>>(BT, FF, E, pxn, pWf1T + f1Off, bf1 + (size_t)l*FF, nullptr, pff);
        gemm_mma<EPI_RES ,0><<<gE, 256, GSM_BYTES>>>(BT, E, FF, pff, pWf2T + f1Off, bf2 + l*E, ph, ph);
    }

    ln_kernel<<<BT, 256>>>(ph, pxn, lnf_g, lnf_b);
    gemm_mma<EPI_BIAS,0><<<gV, 256, GSM_BYTES>>>(BT, VOCAB, E, pxn, pHT, nullptr, nullptr, out);
}

// round 6
// speedup vs baseline: 3.0363x; 1.2716x over previous
#include <cuda_runtime.h>
#include <cuda_fp16.h>
#include <math.h>
#include <stdint.h>

// ---------------- problem constants ----------------
#define LNUM 12
#define E 1024
#define H 16
#define T 512
#define BATCH 8
#define VOCAB 512
#define FF 4096
#define D 64
#define BT (BATCH*T)   // 4096

// ---------------- persistent device scratch ----------------
__device__ float  g_h [BT*E];
__device__ __half g_xn[BT*E];            // half, k-permuted
__device__ float  g_q [BT*E];
__device__ float  g_k [BT*E];
__device__ float  g_v [BT*E];
__device__ __half g_y [BT*E];            // half, k-permuted
__device__ __half g_ff[(size_t)BT*FF];   // half, k-permuted
// transposed (K-major, k-permuted) weights, fp16
__device__ __half g_WqT [(size_t)LNUM*E*E];
__device__ __half g_WkT [(size_t)LNUM*E*E];
__device__ __half g_WvT [(size_t)LNUM*E*E];
__device__ __half g_WpT [(size_t)LNUM*E*E];
__device__ __half g_Wf1T[(size_t)LNUM*E*FF];
__device__ __half g_Wf2T[(size_t)LNUM*FF*E];
__device__ __half g_headT[(size_t)E*VOCAB];

// ---------------- helpers ----------------
__device__ __forceinline__ uint32_t smem_u32(const void* p) {
    uint32_t a;
    asm("{ .reg .u64 t; cvta.to.shared.u64 t, %1; cvt.u32.u64 %0, t; }" : "=r"(a) : "l"(p));
    return a;
}
__device__ __forceinline__ void cp16(uint32_t saddr, const void* g) {
    asm volatile("cp.async.cg.shared.global [%0], [%1], 16;" :: "r"(saddr), "l"(g));
}
__device__ __forceinline__ void cp_commit() {
    asm volatile("cp.async.commit_group;" ::: "memory");
}
template<int N>
__device__ __forceinline__ void cp_wait() {
    asm volatile("cp.async.wait_group %0;" :: "n"(N) : "memory");
}
// m16n8k16 f16 mma, fp32 accumulate
__device__ __forceinline__ void mma_f16(float* d, uint32_t a0, uint32_t a1, uint32_t a2,
                                        uint32_t a3, uint32_t b0, uint32_t b1) {
    asm volatile("mma.sync.aligned.m16n8k16.row.col.f32.f16.f16.f32 "
        "{%0,%1,%2,%3}, {%4,%5,%6,%7}, {%8,%9}, {%0,%1,%2,%3};"
        : "+f"(d[0]), "+f"(d[1]), "+f"(d[2]), "+f"(d[3])
        : "r"(a0), "r"(a1), "r"(a2), "r"(a3), "r"(b0), "r"(b1));
}
// word-permute within each 8-word block: logical word w -> pos (0,4,1,5,2,6,3,7)^-1
__device__ __forceinline__ int perm8(int w) {
    return (w & ~7) | ((w & 3) << 1) | ((w >> 2) & 1);
}
// half-index permutation (pairs of halves = words)
__device__ __forceinline__ int permh(int k) {
    return perm8(k >> 1) * 2 + (k & 1);
}

// ---------------- embedding ----------------
__global__ void embed_kernel(const int* __restrict__ x,
                             const float* __restrict__ tok,
                             const float* __restrict__ pos,
                             float* __restrict__ h)
{
    int idx = blockIdx.x * blockDim.x + threadIdx.x;
    if (idx >= BT*E) return;
    int row = idx >> 10;
    int e   = idx & (E-1);
    int t   = row & (T-1);
    h[idx] = tok[(size_t)x[row]*E + e] + pos[(size_t)t*E + e];
}

// ---------------- layernorm (fp16 k-permuted output) ----------------
__global__ __launch_bounds__(256) void ln_kernel(const float* __restrict__ in,
                                                 __half* __restrict__ out,
                                                 const float* __restrict__ gamma,
                                                 const float* __restrict__ beta)
{
    int row = blockIdx.x;
    const float* xr = in + (size_t)row * E;
    float s = 0.f, ss = 0.f;
    for (int i = threadIdx.x; i < E; i += 256) {
        float v = xr[i]; s += v; ss += v * v;
    }
    #pragma unroll
    for (int o = 16; o > 0; o >>= 1) {
        s  += __shfl_xor_sync(0xffffffffu, s,  o);
        ss += __shfl_xor_sync(0xffffffffu, ss, o);
    }
    __shared__ float sred[8], ssred[8];
    int w = threadIdx.x >> 5;
    if ((threadIdx.x & 31) == 0) { sred[w] = s; ssred[w] = ss; }
    __syncthreads();
    if (threadIdx.x < 32) {
        s  = (threadIdx.x < 8) ? sred [threadIdx.x] : 0.f;
        ss = (threadIdx.x < 8) ? ssred[threadIdx.x] : 0.f;
        #pragma unroll
        for (int o = 4; o > 0; o >>= 1) {
            s  += __shfl_xor_sync(0xffffffffu, s,  o);
            ss += __shfl_xor_sync(0xffffffffu, ss, o);
        }
        if (threadIdx.x == 0) { sred[0] = s; ssred[0] = ss; }
    }
    __syncthreads();
    float mu   = sred[0] * (1.f / E);
    float var  = ssred[0] * (1.f / E) - mu * mu;
    float rstd = rsqrtf(var + 1e-5f);
    __half* orow = out + (size_t)row * E;
    for (int i = threadIdx.x; i < E; i += 256)
        orow[permh(i)] = __float2half_rn((xr[i] - mu) * rstd * gamma[i] + beta[i]);
}

// ---------------- weight transpose ([R,C] fp32 -> [C,R] fp16, k-permuted) --------
__global__ __launch_bounds__(256) void transpose_h(const float* __restrict__ in,
                                                   __half* __restrict__ out, int R, int C)
{
    __shared__ float tile[32][33];
    size_t mat = (size_t)blockIdx.z * R * C;
    int c0 = blockIdx.x * 32, r0 = blockIdx.y * 32;
    #pragma unroll
    for (int j = threadIdx.y; j < 32; j += 8)
        tile[j][threadIdx.x] = in[mat + (size_t)(r0 + j) * C + c0 + threadIdx.x];
    __syncthreads();
    int pk = r0 + permh((int)threadIdx.x);
    #pragma unroll
    for (int j = threadIdx.y; j < 32; j += 8)
        out[mat + (size_t)(c0 + j) * R + pk] = __float2half_rn(tile[threadIdx.x][j]);
}

// ---------------- fp16 mma GEMM (256x128 tile, 8 warps of 64x64, K-tile 64) ------
// C[M,N] = A[M,K] @ Bt[N,K]^T (+bias)(+epilogue). A, Bt fp16 k-permuted.
// smem rows: 64 halves (=32 words) padded to 40 words (160B).
#define EPI_BIAS 0
#define EPI_GELU 1
#define EPI_RES  2
#define TKh 64                        // k per tile (halves)
#define ROWW 40                       // 32-bit words per smem row
#define STG_AW (256*ROWW)             // A words/stage
#define STG_BW (128*ROWW)             // B words/stage
#define STG_W  (STG_AW+STG_BW)
#define STG_B  (STG_W*4)              // 61440 bytes/stage
#define GSM_BYTES (3*STG_B)           // 184320 bytes

template<int EPI, int PERM>
__global__ __launch_bounds__(256) void gemm_mma(int M, int N, int K,
    const __half* __restrict__ A, const __half* __restrict__ Bt,
    const float* __restrict__ bias, const float* __restrict__ res,
    void* __restrict__ Cv)
{
    extern __shared__ uint32_t smw[];
    const uint32_t sbase = smem_u32(smw);
    const int tid  = threadIdx.x;
    const int wid  = tid >> 5, lane = tid & 31;
    const int wm   = wid & 3, wn = wid >> 2;      // 4 x 2 warps, 64x64 each
    const int g    = lane >> 2, c = lane & 3;

    const size_t m0 = (size_t)blockIdx.y * 256;
    const int    n0 = blockIdx.x * 128;
    const int    nK = K / TKh;

    const int ldrow = tid >> 3, ldch = tid & 7;

    auto load_tiles = [&](int kt, int st) {
        const int k0 = kt * TKh;
        const uint32_t sA = sbase + st*STG_B;
        const uint32_t sB = sA + STG_AW*4;
        const __half* Ag = A  + (m0 + ldrow) * K + k0 + ldch*8;
        #pragma unroll
        for (int i = 0; i < 8; i++)
            cp16(sA + (ldrow + i*32)*160 + ldch*16, Ag + (size_t)(i*32) * K);
        const __half* Bg = Bt + (size_t)(n0 + ldrow) * K + k0 + ldch*8;
        #pragma unroll
        for (int i = 0; i < 4; i++)
            cp16(sB + (ldrow + i*32)*160 + ldch*16, Bg + (size_t)(i*32) * K);
        cp_commit();
    };

    float acc[4][8][4];
    #pragma unroll
    for (int mf = 0; mf < 4; mf++)
        #pragma unroll
        for (int nf = 0; nf < 8; nf++)
            #pragma unroll
            for (int i = 0; i < 4; i++) acc[mf][nf][i] = 0.f;

    load_tiles(0, 0);
    load_tiles(1, 1);

    for (int kt = 0; kt < nK; kt++) {
        const int st = kt % 3;
        if (kt < nK - 1) cp_wait<1>(); else cp_wait<0>();
        __syncthreads();
        if (kt + 2 < nK) load_tiles(kt + 2, (kt + 2) % 3);

        const uint32_t* as = smw + st*STG_W;
        const uint32_t* bs = as + STG_AW;
        #pragma unroll
        for (int ks = 0; ks < 4; ks++) {     // 4 x k16 steps per tile
            const int kw = ks*8 + 2*c;
            uint2 av[4][2];
            #pragma unroll
            for (int mf = 0; mf < 4; mf++) {
                int r = wm*64 + mf*16 + g;
                av[mf][0] = *(const uint2*)&as[ r      * ROWW + kw];
                av[mf][1] = *(const uint2*)&as[(r + 8) * ROWW + kw];
            }
            uint2 bv[8];
            #pragma unroll
            for (int nf = 0; nf < 8; nf++)
                bv[nf] = *(const uint2*)&bs[(wn*64 + nf*8 + g) * ROWW + kw];
            #pragma unroll
            for (int mf = 0; mf < 4; mf++)
                #pragma unroll
                for (int nf = 0; nf < 8; nf++)
                    mma_f16(acc[mf][nf],
                            av[mf][0].x, av[mf][1].x, av[mf][0].y, av[mf][1].y,
                            bv[nf].x, bv[nf].y);
        }
        __syncthreads();
    }

    // epilogue
    #pragma unroll
    for (int mf = 0; mf < 4; mf++) {
        size_t r = m0 + wm*64 + mf*16 + g;
        #pragma unroll
        for (int nf = 0; nf < 8; nf++) {
            int col = n0 + wn*64 + nf*8 + c*2;
            float v0 = acc[mf][nf][0], v1 = acc[mf][nf][1];
            float v2 = acc[mf][nf][2], v3 = acc[mf][nf][3];
            if (bias) {
                float bb0 = bias[col], bb1 = bias[col+1];
                v0 += bb0; v1 += bb1; v2 += bb0; v3 += bb1;
            }
            if (EPI == EPI_GELU) {
                v0 = 0.5f*v0*(1.f + erff(v0*0.70710678118654752f));
                v1 = 0.5f*v1*(1.f + erff(v1*0.70710678118654752f));
                v2 = 0.5f*v2*(1.f + erff(v2*0.70710678118654752f));
                v3 = 0.5f*v3*(1.f + erff(v3*0.70710678118654752f));
            }
            if (EPI == EPI_RES) {
                const float* resp = res + r*N + col;
                float2 r0 = *(const float2*)resp;
                float2 r1 = *(const float2*)(resp + 8*N);
                v0 += r0.x; v1 += r0.y; v2 += r1.x; v3 += r1.y;
            }
            if (PERM) {   // half output, k-permuted
                __half* C = (__half*)Cv;
                int p0 = permh(col), p1 = permh(col + 1);
                C[r*N + p0]     = __float2half_rn(v0);
                C[r*N + p1]     = __float2half_rn(v1);
                C[(r+8)*N + p0] = __float2half_rn(v2);
                C[(r+8)*N + p1] = __float2half_rn(v3);
            } else {      // fp32 output
                float* C = (float*)Cv;
                float2 o0 = {v0, v1}, o1 = {v2, v3};
                *(float2*)(C + r*N + col)     = o0;
                *(float2*)(C + (r+8)*N + col) = o1;
            }
        }
    }
}

// ---------------- fused causal attention (fp32; fp16 k-permuted output) ----------
__global__ __launch_bounds__(256) void attn_kernel(const float* __restrict__ Q,
                                                   const float* __restrict__ K,
                                                   const float* __restrict__ V,
                                                   __half* __restrict__ Y)
{
    int bh = blockIdx.y;
    int b  = bh >> 4;
    int h  = bh & 15;
    int qt = blockIdx.x;
    int tid = threadIdx.x;
    int r  = tid >> 2;
    int c4 = tid & 3;

    __shared__ float sK[64][D];
    __shared__ float sV[64][D];

    int qrow = qt * 64 + r;
    const float* qp = Q + ((size_t)(b*T + qrow)) * E + h*D + c4*16;
    float qreg[16];
    #pragma unroll
    for (int i = 0; i < 16; i++) qreg[i] = qp[i] * 0.125f;

    float acc[16];
    #pragma unroll
    for (int i = 0; i < 16; i++) acc[i] = 0.f;
    float mcur = -INFINITY, l = 0.f;

    for (int kt = 0; kt <= qt; kt++) {
        __syncthreads();
        #pragma unroll 4
        for (int i = tid; i < 64*64; i += 256) {
            int kr = i >> 6, kc = i & 63;
            size_t gg = ((size_t)(b*T + kt*64 + kr)) * E + h*D + kc;
            sK[kr][kc] = K[gg];
            sV[kr][kc] = V[gg];
        }
        __syncthreads();

        float s[64];
        #pragma unroll
        for (int k = 0; k < 64; k++) {
            float d = 0.f;
            #pragma unroll
            for (int i = 0; i < 16; i++)
                d = fmaf(qreg[i], sK[k][c4*16 + i], d);
            d += __shfl_xor_sync(0xffffffffu, d, 1);
            d += __shfl_xor_sync(0xffffffffu, d, 2);
            s[k] = d;
        }
        if (kt == qt) {
            #pragma unroll
            for (int k = 0; k < 64; k++)
                if (kt*64 + k > qrow) s[k] = -INFINITY;
        }
        float tmax = mcur;
        #pragma unroll
        for (int k = 0; k < 64; k++) tmax = fmaxf(tmax, s[k]);
        float fac = __expf(mcur - tmax);
        mcur = tmax;
        l *= fac;
        #pragma unroll
        for (int i = 0; i < 16; i++) acc[i] *= fac;
        #pragma unroll
        for (int k = 0; k < 64; k++) {
            float p = __expf(s[k] - mcur);
            l += p;
            #pragma unroll
            for (int i = 0; i < 16; i++)
                acc[i] = fmaf(p, sV[k][c4*16 + i], acc[i]);
        }
    }

    float inv = 1.f / l;
    __half* yrow = Y + ((size_t)(b*T + qrow)) * E;
    int colbase = h*D + c4*16;
    #pragma unroll
    for (int i = 0; i < 16; i++)
        yrow[permh(colbase + i)] = __float2half_rn(acc[i] * inv);
}

// ---------------- host orchestration ----------------
extern "C" void kernel_launch(void* const* d_in, const int* in_sizes, int n_in,
                              void* d_out, int out_size)
{
    (void)in_sizes; (void)n_in; (void)out_size;
    const int*   x     = (const int*)  d_in[0];
    const float* tok   = (const float*)d_in[2];
    const float* pos   = (const float*)d_in[3];
    const float* ln1_g = (const float*)d_in[4];
    const float* ln1_b = (const float*)d_in[5];
    const float* Wq    = (const float*)d_in[6];
    const float* bq    = (const float*)d_in[7];
    const float* Wk    = (const float*)d_in[8];
    const float* bk    = (const float*)d_in[9];
    const float* Wv    = (const float*)d_in[10];
    const float* bv    = (const float*)d_in[11];
    const float* Wp    = (const float*)d_in[12];
    const float* bp    = (const float*)d_in[13];
    const float* ln2_g = (const float*)d_in[14];
    const float* ln2_b = (const float*)d_in[15];
    const float* Wf1   = (const float*)d_in[16];
    const float* bf1   = (const float*)d_in[17];
    const float* Wf2   = (const float*)d_in[18];
    const float* bf2   = (const float*)d_in[19];
    const float* lnf_g = (const float*)d_in[20];
    const float* lnf_b = (const float*)d_in[21];
    const float* headw = (const float*)d_in[22];
    float* out = (float*)d_out;

    float *ph, *pq, *pk, *pv;
    __half *pxn, *py, *pff;
    __half *pWqT, *pWkT, *pWvT, *pWpT, *pWf1T, *pWf2T, *pHT;
    cudaGetSymbolAddress((void**)&ph,   g_h);
    cudaGetSymbolAddress((void**)&pxn,  g_xn);
    cudaGetSymbolAddress((void**)&pq,   g_q);
    cudaGetSymbolAddress((void**)&pk,   g_k);
    cudaGetSymbolAddress((void**)&pv,   g_v);
    cudaGetSymbolAddress((void**)&py,   g_y);
    cudaGetSymbolAddress((void**)&pff,  g_ff);
    cudaGetSymbolAddress((void**)&pWqT, g_WqT);
    cudaGetSymbolAddress((void**)&pWkT, g_WkT);
    cudaGetSymbolAddress((void**)&pWvT, g_WvT);
    cudaGetSymbolAddress((void**)&pWpT, g_WpT);
    cudaGetSymbolAddress((void**)&pWf1T, g_Wf1T);
    cudaGetSymbolAddress((void**)&pWf2T, g_Wf2T);
    cudaGetSymbolAddress((void**)&pHT,  g_headT);

    cudaFuncSetAttribute(gemm_mma<EPI_BIAS,0>, cudaFuncAttributeMaxDynamicSharedMemorySize, GSM_BYTES);
    cudaFuncSetAttribute(gemm_mma<EPI_GELU,1>, cudaFuncAttributeMaxDynamicSharedMemorySize, GSM_BYTES);
    cudaFuncSetAttribute(gemm_mma<EPI_RES ,0>, cudaFuncAttributeMaxDynamicSharedMemorySize, GSM_BYTES);

    dim3 tb(32, 8);
    dim3 gE(E/128,     BT/256);   // (8,16)
    dim3 gF(FF/128,    BT/256);   // (32,16)
    dim3 gV(VOCAB/128, BT/256);   // (4,16)
    dim3 gAtt(T/64, BATCH*H);

    // launches ordered so index 5 (ncu -s 5 -c 1) is the first GEMM
    transpose_h<<<dim3(E/32,  E/32,  LNUM), tb>>>(Wq,  pWqT,  E,  E);       // 0
    transpose_h<<<dim3(E/32,  E/32,  LNUM), tb>>>(Wk,  pWkT,  E,  E);       // 1
    transpose_h<<<dim3(E/32,  E/32,  LNUM), tb>>>(Wv,  pWvT,  E,  E);       // 2
    embed_kernel<<<(BT*E + 255)/256, 256>>>(x, tok, pos, ph);               // 3
    ln_kernel<<<BT, 256>>>(ph, pxn, ln1_g, ln1_b);                          // 4
    gemm_mma<EPI_BIAS,0><<<gE, 256, GSM_BYTES>>>(BT, E, E, pxn, pWqT, bq, nullptr, pq);  // 5 <- profiled
    transpose_h<<<dim3(E/32,  E/32,  LNUM), tb>>>(Wp,  pWpT,  E,  E);
    transpose_h<<<dim3(FF/32, E/32,  LNUM), tb>>>(Wf1, pWf1T, E,  FF);
    transpose_h<<<dim3(E/32,  FF/32, LNUM), tb>>>(Wf2, pWf2T, FF, E);
    transpose_h<<<dim3(VOCAB/32, E/32, 1),  tb>>>(headw, pHT, E,  VOCAB);

    for (int l = 0; l < LNUM; l++) {
        const size_t wOff  = (size_t)l * E * E;
        const size_t f1Off = (size_t)l * E * FF;
        if (l > 0) {
            ln_kernel<<<BT, 256>>>(ph, pxn, ln1_g + l*E, ln1_b + l*E);
            gemm_mma<EPI_BIAS,0><<<gE, 256, GSM_BYTES>>>(BT, E, E, pxn, pWqT + wOff, bq + l*E, nullptr, pq);
        }
        gemm_mma<EPI_BIAS,0><<<gE, 256, GSM_BYTES>>>(BT, E, E, pxn, pWkT + wOff, bk + l*E, nullptr, pk);
        gemm_mma<EPI_BIAS,0><<<gE, 256, GSM_BYTES>>>(BT, E, E, pxn, pWvT + wOff, bv + l*E, nullptr, pv);
        attn_kernel<<<gAtt, 256>>>(pq, pk, pv, py);
        gemm_mma<EPI_RES ,0><<<gE, 256, GSM_BYTES>>>(BT, E, E, py, pWpT + wOff, bp + l*E, ph, ph);
        ln_kernel<<<BT, 256>>>(ph, pxn, ln2_g + l*E, ln2_b + l*E);
        gemm_mma<EPI_GELU,1><<<gF, 256, GSM_BYTES>>>(BT, FF, E, pxn, pWf1T + f1Off, bf1 + (size_t)l*FF, nullptr, pff);
        gemm_mma<EPI_RES ,0><<<gE, 256, GSM_BYTES>>>(BT, E, FF, pff, pWf2T + f1Off, bf2 + l*E, ph, ph);
    }

    ln_kernel<<<BT, 256>>>(ph, pxn, lnf_g, lnf_b);
    gemm_mma<EPI_BIAS,0><<<gV, 256, GSM_BYTES>>>(BT, VOCAB, E, pxn, pHT, nullptr, nullptr, out);
}